// round 13
// baseline (speedup 1.0000x reference)
#include <cuda_runtime.h>

// ---------------------------------------------------------------------------
// TwoBodySphericalHarmonicTensorEmbed
//   out[e, c, j] = sh_j(edge_vec[e]) * w[e, c, widx[j]]
//   w[e, c, i]   = dot(edge_invariants[e, :64], W_lin[:, 3c+i])
//   widx = {0,1,1,1,2,2,2,2,2}
//
// R12: 512-thread CTAs, 2/SM (32 warps/SM, was 16). smem: W copy (48KB) +
// per-edge w rows (stride 196) with the A staging tile ALIASED into the w
// region (extra barrier orders GEMM reads vs w writes). Epilogue reads w via
// LDS.128 and recomputes sh per-thread (no sh smem). f32x2-packed GEMM.
// ---------------------------------------------------------------------------

#define NTHREADS 512
#define E_TILE   64
#define E_STR    196                   // w row stride in floats (192 used)

// smem layout (floats)
#define W_SZ     (64 * 192)            // 12288
#define WR_OFF   (W_SZ)                // w rows: [e=64][E_STR]; A_t aliases front
#define WR_SZ    (E_TILE * E_STR)      // 12544
#define SMEM_FLOATS (WR_OFF + WR_SZ)   // 24832 floats = 99328 B

__device__ __forceinline__ unsigned long long pack2(float lo, float hi) {
    unsigned long long r;
    asm("mov.b64 %0, {%1, %2};" : "=l"(r) : "f"(lo), "f"(hi));
    return r;
}
__device__ __forceinline__ void fma2(unsigned long long& d,
                                     unsigned long long a,
                                     unsigned long long b) {
    asm("fma.rn.f32x2 %0, %1, %2, %0;" : "+l"(d) : "l"(a), "l"(b));
}
__device__ __forceinline__ void unpack2(unsigned long long v, float& lo, float& hi) {
    asm("mov.b64 {%0, %1}, %2;" : "=f"(lo), "=f"(hi) : "l"(v));
}

__global__ void __launch_bounds__(NTHREADS, 2)
embed_kernel(const float* __restrict__ edge_vec,
             const float* __restrict__ EI,       // [E, 64]
             const float* __restrict__ Wg,       // [64, 192]
             float* __restrict__ out,            // [E, 64, 9]
             int E, int ntiles)
{
    extern __shared__ float smem[];
    float* W_s  = smem;
    float* wr_s = smem + WR_OFF;       // [e][n], stride E_STR
    float* A_t  = wr_s;                // ALIAS: [k=64][e=64], swizzled; dead
                                       // before wr_s is written (barrier C)

    const int tid = threadIdx.x;

    // ---- stage W_lin once per block (persistent grid) ----
    {
        const float4* wg4 = reinterpret_cast<const float4*>(Wg);
        float4* ws4 = reinterpret_cast<float4*>(W_s);
        #pragma unroll
        for (int i = 0; i < 6; i++)
            ws4[tid + i * NTHREADS] = wg4[tid + i * NTHREADS];
    }

    // GEMM mapping: channel c (0..63), edge group of 8 (eg 0..7)
    const int c  = tid & 63;
    const int eg = tid >> 6;
    const int e0 = eg * 8;

    // epilogue mapping: edge (0..63), 8-channel group (0..7)
    const int ep_e  = tid >> 3;
    const int ep_cg = tid & 7;

    for (int tile = blockIdx.x; tile < ntiles; tile += gridDim.x) {
        const int ebase = tile * E_TILE;

        __syncthreads();  // (A) prev epilogue done reading wr_s before A_t clobbers

        // ---- stage A tile, transposed + XOR-swizzled: A_t[k][e ^ sw(k)] ----
        #pragma unroll
        for (int iter = 0; iter < 2; iter++) {
            const int f  = iter * NTHREADS + tid;   // 0..1023
            const int e  = f >> 4;                  // 0..63
            const int kq = f & 15;                  // float4 index along k
            const int eglob = ebase + e;
            float4 v = make_float4(0.f, 0.f, 0.f, 0.f);
            if (eglob < E)
                v = *reinterpret_cast<const float4*>(EI + (size_t)eglob * 64 + kq * 4);
            const float vv[4] = {v.x, v.y, v.z, v.w};
            #pragma unroll
            for (int i = 0; i < 4; i++) {
                const int k  = kq * 4 + i;
                const int sw = ((k & 7) ^ ((k >> 3) & 7)) << 2;
                A_t[k * E_TILE + (e ^ sw)] = vv[i];
            }
        }

        __syncthreads();  // (B) A_t visible

        // ---- GEMM: acc[ir][p] = f32x2 over edge pairs (e0+2p, e0+2p+1) ----
        unsigned long long acc[3][4];
        #pragma unroll
        for (int ir = 0; ir < 3; ir++)
            #pragma unroll
            for (int p = 0; p < 4; p++) acc[ir][p] = 0ull;

        #pragma unroll 8
        for (int k = 0; k < 64; k++) {
            const int sw = ((k & 7) ^ ((k >> 3) & 7)) << 2;
            const float* arow = A_t + k * E_TILE;
            const ulonglong2 a01 =
                *reinterpret_cast<const ulonglong2*>(arow + (e0 ^ sw));
            const ulonglong2 a23 =
                *reinterpret_cast<const ulonglong2*>(arow + ((e0 + 4) ^ sw));
            const float* wr = W_s + k * 192 + 3 * c;
            const unsigned long long pw0 = pack2(wr[0], wr[0]);
            const unsigned long long pw1 = pack2(wr[1], wr[1]);
            const unsigned long long pw2 = pack2(wr[2], wr[2]);
            fma2(acc[0][0], a01.x, pw0); fma2(acc[0][1], a01.y, pw0);
            fma2(acc[0][2], a23.x, pw0); fma2(acc[0][3], a23.y, pw0);
            fma2(acc[1][0], a01.x, pw1); fma2(acc[1][1], a01.y, pw1);
            fma2(acc[1][2], a23.x, pw1); fma2(acc[1][3], a23.y, pw1);
            fma2(acc[2][0], a01.x, pw2); fma2(acc[2][1], a01.y, pw2);
            fma2(acc[2][2], a23.x, pw2); fma2(acc[2][3], a23.y, pw2);
        }

        __syncthreads();  // (C) all GEMM reads of A_t done; wr_s may clobber it

        // ---- write w rows: wr_s[e][3c+ir] (conflict-free: 3c mod 32 distinct) ----
        #pragma unroll
        for (int ir = 0; ir < 3; ir++) {
            #pragma unroll
            for (int p = 0; p < 4; p++) {
                float lo, hi;
                unpack2(acc[ir][p], lo, hi);
                wr_s[(e0 + 2 * p)     * E_STR + 3 * c + ir] = lo;
                wr_s[(e0 + 2 * p + 1) * E_STR + 3 * c + ir] = hi;
            }
        }

        __syncthreads();  // (D) wr_s visible

        // ---- epilogue: thread = (edge, 8-channel group) ----
        const int eglob = ebase + ep_e;
        if (eglob < E) {
            // recompute sh (cheap; avoids an smem array + extra staging phase)
            float sh9[9];
            {
                const float vx = edge_vec[(size_t)eglob * 3 + 0];
                const float vy = edge_vec[(size_t)eglob * 3 + 1];
                const float vz = edge_vec[(size_t)eglob * 3 + 2];
                const float inv = rsqrtf(vx * vx + vy * vy + vz * vz);
                const float x = vx * inv, y = vy * inv, z = vz * inv;
                const float SQ3  = 1.7320508075688772f;
                const float SQ5  = 2.2360679774997896f;
                const float SQ15 = 3.8729833462074170f;
                sh9[0] = 1.0f;
                sh9[1] = SQ3 * x;
                sh9[2] = SQ3 * y;
                sh9[3] = SQ3 * z;
                sh9[4] = SQ15 * x * z;
                sh9[5] = SQ15 * x * y;
                sh9[6] = SQ5 * (y * y - 0.5f * (x * x + z * z));
                sh9[7] = SQ15 * y * z;
                sh9[8] = (SQ15 * 0.5f) * (z * z - x * x);
            }

            // 24 w values (8 channels x 3 irreps) via 6x LDS.128
            float4 wv4[6];
            const float4* wrow = reinterpret_cast<const float4*>(
                wr_s + ep_e * E_STR + ep_cg * 24);
            #pragma unroll
            for (int q = 0; q < 6; q++) wv4[q] = wrow[q];
            const float* wv = reinterpret_cast<const float*>(wv4);

            const int WIDX[9] = {0, 1, 1, 1, 2, 2, 2, 2, 2};
            float4* ob = reinterpret_cast<float4*>(
                out + (size_t)eglob * 576 + ep_cg * 72);

            #pragma unroll
            for (int f = 0; f < 18; f++) {
                float t[4];
                #pragma unroll
                for (int q = 0; q < 4; q++) {
                    const int idx = 4 * f + q;     // 0..71 (compile-time)
                    const int u = idx / 9;
                    const int j = idx % 9;
                    t[q] = sh9[j] * wv[3 * u + WIDX[j]];
                }
                float4 v;
                v.x = t[0]; v.y = t[1]; v.z = t[2]; v.w = t[3];
                __stcs(ob + f, v);  // streaming: output never re-read
            }
        }
    }
}

extern "C" void kernel_launch(void* const* d_in, const int* in_sizes, int n_in,
                              void* d_out, int out_size)
{
    const float* edge_vec = (const float*)d_in[0];
    const float* EI       = (const float*)d_in[1];
    const float* Wg       = (const float*)d_in[2];
    float* out            = (float*)d_out;

    const int E      = in_sizes[0] / 3;
    const int ntiles = (E + E_TILE - 1) / E_TILE;

    const int smem_bytes = SMEM_FLOATS * sizeof(float);  // 99328 B
    cudaFuncSetAttribute(embed_kernel,
                         cudaFuncAttributeMaxDynamicSharedMemorySize,
                         smem_bytes);

    int grid = 304;  // 2 CTAs/SM persistent
    if (grid > ntiles) grid = ntiles;

    embed_kernel<<<grid, NTHREADS, smem_bytes>>>(edge_vec, EI, Wg, out, E, ntiles);
}

// round 14
// speedup vs baseline: 1.2317x; 1.2317x over previous
#include <cuda_runtime.h>

// ---------------------------------------------------------------------------
// TwoBodySphericalHarmonicTensorEmbed
//   out[e, c, j] = sh_j(edge_vec[e]) * w[e, c, widx[j]]
//   w[e, c, i]   = dot(edge_invariants[e, :64], W_lin[:, 3c+i])
//   widx = {0,1,1,1,2,2,2,2,2}
//
// R14: back to 256-thr / 2 CTA (R11's healthy reg budget), but 16 edges per
// GEMM thread (24 f32x2 accumulators) so each W-load+pack triple feeds 24
// FFMA2 instead of 12. E_TILE=64. A tile aliased into the w-staging region
// (98KB smem). Epilogue: 4 thr/edge, w via LDS.128, sh recomputed, 36x
// streaming STG.128 per thread.
// ---------------------------------------------------------------------------

#define NTHREADS 256
#define E_TILE   64
#define E_STR    196                   // w row stride in floats (192 used)

// smem layout (floats)
#define W_SZ     (64 * 192)            // 12288
#define WR_OFF   (W_SZ)                // w rows [e=64][E_STR]; A_t aliases front
#define WR_SZ    (E_TILE * E_STR)      // 12544  (A_t needs 64*64=4096, fits)
#define SMEM_FLOATS (WR_OFF + WR_SZ)   // 24832 floats = 99328 B

__device__ __forceinline__ unsigned long long pack2(float lo, float hi) {
    unsigned long long r;
    asm("mov.b64 %0, {%1, %2};" : "=l"(r) : "f"(lo), "f"(hi));
    return r;
}
__device__ __forceinline__ void fma2(unsigned long long& d,
                                     unsigned long long a,
                                     unsigned long long b) {
    asm("fma.rn.f32x2 %0, %1, %2, %0;" : "+l"(d) : "l"(a), "l"(b));
}
__device__ __forceinline__ void unpack2(unsigned long long v, float& lo, float& hi) {
    asm("mov.b64 {%0, %1}, %2;" : "=f"(lo), "=f"(hi) : "l"(v));
}

__global__ void __launch_bounds__(NTHREADS, 2)
embed_kernel(const float* __restrict__ edge_vec,
             const float* __restrict__ EI,       // [E, 64]
             const float* __restrict__ Wg,       // [64, 192]
             float* __restrict__ out,            // [E, 64, 9]
             int E, int ntiles)
{
    extern __shared__ float smem[];
    float* W_s  = smem;
    float* wr_s = smem + WR_OFF;       // [e][n], stride E_STR
    float* A_t  = wr_s;                // ALIAS: [k=64][e=64], swizzled; dead
                                       // before wr_s is written (barrier C)

    const int tid = threadIdx.x;

    // ---- stage W_lin once per block (persistent grid) ----
    {
        const float4* wg4 = reinterpret_cast<const float4*>(Wg);
        float4* ws4 = reinterpret_cast<float4*>(W_s);
        #pragma unroll
        for (int i = 0; i < 12; i++)
            ws4[tid + i * NTHREADS] = wg4[tid + i * NTHREADS];
    }

    // GEMM mapping: channel c (0..63), 16-edge group (eg 0..3)
    const int c  = tid & 63;
    const int eg = tid >> 6;
    const int e0 = eg * 16;

    // epilogue mapping: edge (0..63), 16-channel group (cg 0..3)
    const int ep_e  = tid >> 2;
    const int ep_cg = tid & 3;

    for (int tile = blockIdx.x; tile < ntiles; tile += gridDim.x) {
        const int ebase = tile * E_TILE;

        __syncthreads();  // (A) prev epilogue done reading wr_s before A_t clobbers

        // ---- stage A tile, transposed + XOR-swizzled: A_t[k][e ^ sw(k)] ----
        #pragma unroll
        for (int iter = 0; iter < 4; iter++) {
            const int f  = iter * NTHREADS + tid;   // 0..1023
            const int e  = f >> 4;                  // 0..63
            const int kq = f & 15;                  // float4 index along k
            const int eglob = ebase + e;
            float4 v = make_float4(0.f, 0.f, 0.f, 0.f);
            if (eglob < E)
                v = *reinterpret_cast<const float4*>(EI + (size_t)eglob * 64 + kq * 4);
            const float vv[4] = {v.x, v.y, v.z, v.w};
            #pragma unroll
            for (int i = 0; i < 4; i++) {
                const int k  = kq * 4 + i;
                const int sw = ((k & 7) ^ ((k >> 3) & 7)) << 2;   // flips bits 2..4
                A_t[k * E_TILE + (e ^ sw)] = vv[i];
            }
        }

        __syncthreads();  // (B) A_t visible

        // ---- GEMM: 24 f32x2 accumulators = 8 edge pairs x 3 irreps ----
        unsigned long long acc[3][8];
        #pragma unroll
        for (int ir = 0; ir < 3; ir++)
            #pragma unroll
            for (int p = 0; p < 8; p++) acc[ir][p] = 0ull;

        #pragma unroll 4
        for (int k = 0; k < 64; k++) {
            const int sw = ((k & 7) ^ ((k >> 3) & 7)) << 2;
            const float* arow = A_t + k * E_TILE;
            // 4x LDS.128, warp-broadcast (all lanes in a warp share eg)
            const ulonglong2 a01 =
                *reinterpret_cast<const ulonglong2*>(arow + ((e0 +  0) ^ sw));
            const ulonglong2 a23 =
                *reinterpret_cast<const ulonglong2*>(arow + ((e0 +  4) ^ sw));
            const ulonglong2 a45 =
                *reinterpret_cast<const ulonglong2*>(arow + ((e0 +  8) ^ sw));
            const ulonglong2 a67 =
                *reinterpret_cast<const ulonglong2*>(arow + ((e0 + 12) ^ sw));
            const float* wr = W_s + k * 192 + 3 * c;   // banks 3c mod 32 distinct
            const unsigned long long pw0 = pack2(wr[0], wr[0]);
            const unsigned long long pw1 = pack2(wr[1], wr[1]);
            const unsigned long long pw2 = pack2(wr[2], wr[2]);

            fma2(acc[0][0], a01.x, pw0); fma2(acc[0][1], a01.y, pw0);
            fma2(acc[0][2], a23.x, pw0); fma2(acc[0][3], a23.y, pw0);
            fma2(acc[0][4], a45.x, pw0); fma2(acc[0][5], a45.y, pw0);
            fma2(acc[0][6], a67.x, pw0); fma2(acc[0][7], a67.y, pw0);

            fma2(acc[1][0], a01.x, pw1); fma2(acc[1][1], a01.y, pw1);
            fma2(acc[1][2], a23.x, pw1); fma2(acc[1][3], a23.y, pw1);
            fma2(acc[1][4], a45.x, pw1); fma2(acc[1][5], a45.y, pw1);
            fma2(acc[1][6], a67.x, pw1); fma2(acc[1][7], a67.y, pw1);

            fma2(acc[2][0], a01.x, pw2); fma2(acc[2][1], a01.y, pw2);
            fma2(acc[2][2], a23.x, pw2); fma2(acc[2][3], a23.y, pw2);
            fma2(acc[2][4], a45.x, pw2); fma2(acc[2][5], a45.y, pw2);
            fma2(acc[2][6], a67.x, pw2); fma2(acc[2][7], a67.y, pw2);
        }

        __syncthreads();  // (C) all GEMM reads of A_t done; wr_s may clobber it

        // ---- write w rows: wr_s[e][3c+ir] (banks 3c+ir distinct mod 32) ----
        #pragma unroll
        for (int ir = 0; ir < 3; ir++) {
            #pragma unroll
            for (int p = 0; p < 8; p++) {
                float lo, hi;
                unpack2(acc[ir][p], lo, hi);
                wr_s[(e0 + 2 * p)     * E_STR + 3 * c + ir] = lo;
                wr_s[(e0 + 2 * p + 1) * E_STR + 3 * c + ir] = hi;
            }
        }

        __syncthreads();  // (D) wr_s visible

        // ---- epilogue: thread = (edge, 16-channel group) ----
        const int eglob = ebase + ep_e;
        if (eglob < E) {
            // recompute sh (cheap; avoids an smem array + extra staging phase)
            float sh9[9];
            {
                const float vx = edge_vec[(size_t)eglob * 3 + 0];
                const float vy = edge_vec[(size_t)eglob * 3 + 1];
                const float vz = edge_vec[(size_t)eglob * 3 + 2];
                const float inv = rsqrtf(vx * vx + vy * vy + vz * vz);
                const float x = vx * inv, y = vy * inv, z = vz * inv;
                const float SQ3  = 1.7320508075688772f;
                const float SQ5  = 2.2360679774997896f;
                const float SQ15 = 3.8729833462074170f;
                sh9[0] = 1.0f;
                sh9[1] = SQ3 * x;
                sh9[2] = SQ3 * y;
                sh9[3] = SQ3 * z;
                sh9[4] = SQ15 * x * z;
                sh9[5] = SQ15 * x * y;
                sh9[6] = SQ5 * (y * y - 0.5f * (x * x + z * z));
                sh9[7] = SQ15 * y * z;
                sh9[8] = (SQ15 * 0.5f) * (z * z - x * x);
            }

            // 48 w values (16 channels x 3 irreps) via 12x LDS.128
            float4 wv4[12];
            const float4* wrow = reinterpret_cast<const float4*>(
                wr_s + ep_e * E_STR + ep_cg * 48);
            #pragma unroll
            for (int q = 0; q < 12; q++) wv4[q] = wrow[q];
            const float* wv = reinterpret_cast<const float*>(wv4);

            const int WIDX[9] = {0, 1, 1, 1, 2, 2, 2, 2, 2};
            float4* ob = reinterpret_cast<float4*>(
                out + (size_t)eglob * 576 + ep_cg * 144);

            #pragma unroll
            for (int f = 0; f < 36; f++) {
                float t[4];
                #pragma unroll
                for (int q = 0; q < 4; q++) {
                    const int idx = 4 * f + q;     // 0..143 (compile-time)
                    const int u = idx / 9;         // local channel 0..15
                    const int j = idx % 9;
                    t[q] = sh9[j] * wv[3 * u + WIDX[j]];
                }
                float4 v;
                v.x = t[0]; v.y = t[1]; v.z = t[2]; v.w = t[3];
                __stcs(ob + f, v);  // streaming: output never re-read
            }
        }
    }
}

extern "C" void kernel_launch(void* const* d_in, const int* in_sizes, int n_in,
                              void* d_out, int out_size)
{
    const float* edge_vec = (const float*)d_in[0];
    const float* EI       = (const float*)d_in[1];
    const float* Wg       = (const float*)d_in[2];
    float* out            = (float*)d_out;

    const int E      = in_sizes[0] / 3;
    const int ntiles = (E + E_TILE - 1) / E_TILE;

    const int smem_bytes = SMEM_FLOATS * sizeof(float);  // 99328 B
    cudaFuncSetAttribute(embed_kernel,
                         cudaFuncAttributeMaxDynamicSharedMemorySize,
                         smem_bytes);

    int grid = 304;  // 2 CTAs/SM persistent on 152-SM GB300
    if (grid > ntiles) grid = ntiles;

    embed_kernel<<<grid, NTHREADS, smem_bytes>>>(edge_vec, EI, Wg, out, E, ntiles);
}

// round 15
// speedup vs baseline: 1.6737x; 1.3588x over previous
#include <cuda_runtime.h>

// ---------------------------------------------------------------------------
// TwoBodySphericalHarmonicTensorEmbed
//   out[e, c, j] = sh_j(edge_vec[e]) * w[e, c, widx[j]]
//   w[e, c, i]   = dot(edge_invariants[e, :64], W_lin[:, 3c+i])
//   widx = {0,1,1,1,2,2,2,2,2}
//
// R15: E_TILE=64, 16 edges per GEMM thread (24 f32x2 acc) to halve GEMM LDS
// wavefronts; register-light TWO-PASS epilogue (8 channels per pass) to avoid
// R14's spills; next-tile A prefetched into registers after the GEMM barrier
// (LDG hidden under epilogue); edge_vec prefetched at loop top (hidden under
// GEMM). 3 barriers per 64-edge tile. smem 112KB/CTA, 2 CTAs/SM, 256 thr.
// ---------------------------------------------------------------------------

#define NTHREADS 256
#define E_TILE   64
#define E_STR    192                   // wr_s row stride (floats)

// smem layout (floats)
#define W_SZ     (64 * 192)            // 12288
#define A_OFF    (W_SZ)                // A_t: [k=64][e=64], XOR-swizzled
#define A_SZ     (64 * 64)             // 4096
#define WR_OFF   (A_OFF + A_SZ)        // wr_s: [e=64][192]
#define WR_SZ    (E_TILE * E_STR)      // 12288
#define SMEM_FLOATS (WR_OFF + WR_SZ)   // 28672 floats = 114688 B = 112KB

__device__ __forceinline__ unsigned long long pack2(float lo, float hi) {
    unsigned long long r;
    asm("mov.b64 %0, {%1, %2};" : "=l"(r) : "f"(lo), "f"(hi));
    return r;
}
__device__ __forceinline__ void fma2(unsigned long long& d,
                                     unsigned long long a,
                                     unsigned long long b) {
    asm("fma.rn.f32x2 %0, %1, %2, %0;" : "+l"(d) : "l"(a), "l"(b));
}
__device__ __forceinline__ void unpack2(unsigned long long v, float& lo, float& hi) {
    asm("mov.b64 {%0, %1}, %2;" : "=f"(lo), "=f"(hi) : "l"(v));
}

__global__ void __launch_bounds__(NTHREADS, 2)
embed_kernel(const float* __restrict__ edge_vec,
             const float* __restrict__ EI,       // [E, 64]
             const float* __restrict__ Wg,       // [64, 192]
             float* __restrict__ out,            // [E, 64, 9]
             int E, int ntiles)
{
    extern __shared__ float smem[];
    float* W_s  = smem;
    float* A_t  = smem + A_OFF;
    float* wr_s = smem + WR_OFF;

    const int tid = threadIdx.x;

    // ---- stage W_lin once per block (persistent grid) ----
    {
        const float4* wg4 = reinterpret_cast<const float4*>(Wg);
        float4* ws4 = reinterpret_cast<float4*>(W_s);
        #pragma unroll
        for (int i = 0; i < 12; i++)
            ws4[tid + i * NTHREADS] = wg4[tid + i * NTHREADS];
    }

    // GEMM mapping: channel c (0..63), 16-edge group (eg 0..3)
    const int c  = tid & 63;
    const int eg = tid >> 6;
    const int e0 = eg * 16;

    // epilogue mapping: edge base (0..31, +32 in pass 1), 8-channel group
    const int ep_eb = tid >> 3;
    const int ep_cg = tid & 7;

    const int grid = gridDim.x;
    int tile = blockIdx.x;

    // ---- prologue: stage A(tile0) directly ----
    if (tile < ntiles) {
        #pragma unroll
        for (int it = 0; it < 4; it++) {
            const int f  = it * NTHREADS + tid;   // 0..1023
            const int e  = f >> 4;                // 0..63
            const int kq = f & 15;
            const int eglob = tile * E_TILE + e;
            float4 v = make_float4(0.f, 0.f, 0.f, 0.f);
            if (eglob < E)
                v = *reinterpret_cast<const float4*>(EI + (size_t)eglob * 64 + kq * 4);
            const float vv[4] = {v.x, v.y, v.z, v.w};
            #pragma unroll
            for (int i = 0; i < 4; i++) {
                const int k  = kq * 4 + i;
                const int sw = ((k & 7) ^ ((k >> 3) & 7)) << 2;
                A_t[k * E_TILE + (e ^ sw)] = vv[i];
            }
        }
    }
    __syncthreads();   // W_s + A_t(tile0) visible

    for (; tile < ntiles; tile += grid) {
        const int ebase = tile * E_TILE;

        // ---- prefetch edge_vec for this tile's epilogue (hidden under GEMM) ----
        float evx[2], evy[2], evz[2];
        #pragma unroll
        for (int p = 0; p < 2; p++) {
            const int eglob = ebase + p * 32 + ep_eb;
            evx[p] = evy[p] = evz[p] = 0.f;
            if (eglob < E) {
                evx[p] = __ldg(edge_vec + (size_t)eglob * 3 + 0);
                evy[p] = __ldg(edge_vec + (size_t)eglob * 3 + 1);
                evz[p] = __ldg(edge_vec + (size_t)eglob * 3 + 2);
            }
        }

        // ---- GEMM: 24 f32x2 accumulators = 8 edge pairs x 3 irreps ----
        unsigned long long acc[3][8];
        #pragma unroll
        for (int ir = 0; ir < 3; ir++)
            #pragma unroll
            for (int p = 0; p < 8; p++) acc[ir][p] = 0ull;

        #pragma unroll 8
        for (int k = 0; k < 64; k++) {
            const int sw = ((k & 7) ^ ((k >> 3) & 7)) << 2;
            const float* arow = A_t + k * E_TILE;
            const ulonglong2 a01 =
                *reinterpret_cast<const ulonglong2*>(arow + ((e0 +  0) ^ sw));
            const ulonglong2 a23 =
                *reinterpret_cast<const ulonglong2*>(arow + ((e0 +  4) ^ sw));
            const ulonglong2 a45 =
                *reinterpret_cast<const ulonglong2*>(arow + ((e0 +  8) ^ sw));
            const ulonglong2 a67 =
                *reinterpret_cast<const ulonglong2*>(arow + ((e0 + 12) ^ sw));
            const float* wr = W_s + k * 192 + 3 * c;   // banks 3c+ir distinct
            const unsigned long long pw0 = pack2(wr[0], wr[0]);
            const unsigned long long pw1 = pack2(wr[1], wr[1]);
            const unsigned long long pw2 = pack2(wr[2], wr[2]);

            fma2(acc[0][0], a01.x, pw0); fma2(acc[0][1], a01.y, pw0);
            fma2(acc[0][2], a23.x, pw0); fma2(acc[0][3], a23.y, pw0);
            fma2(acc[0][4], a45.x, pw0); fma2(acc[0][5], a45.y, pw0);
            fma2(acc[0][6], a67.x, pw0); fma2(acc[0][7], a67.y, pw0);

            fma2(acc[1][0], a01.x, pw1); fma2(acc[1][1], a01.y, pw1);
            fma2(acc[1][2], a23.x, pw1); fma2(acc[1][3], a23.y, pw1);
            fma2(acc[1][4], a45.x, pw1); fma2(acc[1][5], a45.y, pw1);
            fma2(acc[1][6], a67.x, pw1); fma2(acc[1][7], a67.y, pw1);

            fma2(acc[2][0], a01.x, pw2); fma2(acc[2][1], a01.y, pw2);
            fma2(acc[2][2], a23.x, pw2); fma2(acc[2][3], a23.y, pw2);
            fma2(acc[2][4], a45.x, pw2); fma2(acc[2][5], a45.y, pw2);
            fma2(acc[2][6], a67.x, pw2); fma2(acc[2][7], a67.y, pw2);
        }

        __syncthreads();   // (C) all A_t reads done

        // ---- prefetch next A tile into registers (LDG hidden under epilogue)
        const int ntile = tile + grid;
        float4 pr[4];
        #pragma unroll
        for (int it = 0; it < 4; it++) {
            const int f  = it * NTHREADS + tid;
            const int e  = f >> 4;
            const int eglob = ntile * E_TILE + e;
            pr[it] = make_float4(0.f, 0.f, 0.f, 0.f);
            if (ntile < ntiles && eglob < E)
                pr[it] = __ldg(reinterpret_cast<const float4*>(
                    EI + (size_t)eglob * 64 + (f & 15) * 4));
        }

        // ---- write w rows: wr_s[e][3c+ir] (conflict-free within warp) ----
        #pragma unroll
        for (int ir = 0; ir < 3; ir++) {
            #pragma unroll
            for (int p = 0; p < 8; p++) {
                float lo, hi;
                unpack2(acc[ir][p], lo, hi);
                wr_s[(e0 + 2 * p)     * E_STR + 3 * c + ir] = lo;
                wr_s[(e0 + 2 * p + 1) * E_STR + 3 * c + ir] = hi;
            }
        }

        __syncthreads();   // (D) wr_s visible

        // ---- epilogue: two passes, 8 threads/edge, 8 channels each ----
        #pragma unroll
        for (int pass = 0; pass < 2; pass++) {
            const int ep_e  = pass * 32 + ep_eb;
            const int eglob = ebase + ep_e;
            if (eglob < E) {
                float sh9[9];
                {
                    const float vx = evx[pass], vy = evy[pass], vz = evz[pass];
                    const float inv = rsqrtf(vx * vx + vy * vy + vz * vz);
                    const float x = vx * inv, y = vy * inv, z = vz * inv;
                    const float SQ3  = 1.7320508075688772f;
                    const float SQ5  = 2.2360679774997896f;
                    const float SQ15 = 3.8729833462074170f;
                    sh9[0] = 1.0f;
                    sh9[1] = SQ3 * x;
                    sh9[2] = SQ3 * y;
                    sh9[3] = SQ3 * z;
                    sh9[4] = SQ15 * x * z;
                    sh9[5] = SQ15 * x * y;
                    sh9[6] = SQ5 * (y * y - 0.5f * (x * x + z * z));
                    sh9[7] = SQ15 * y * z;
                    sh9[8] = (SQ15 * 0.5f) * (z * z - x * x);
                }

                // 24 w values (8 channels x 3 irreps) via 6x LDS.128
                float4 wv4[6];
                const float4* wrow = reinterpret_cast<const float4*>(
                    wr_s + ep_e * E_STR + ep_cg * 24);
                #pragma unroll
                for (int q = 0; q < 6; q++) wv4[q] = wrow[q];
                const float* wv = reinterpret_cast<const float*>(wv4);

                const int WIDX[9] = {0, 1, 1, 1, 2, 2, 2, 2, 2};
                float4* ob = reinterpret_cast<float4*>(
                    out + (size_t)eglob * 576 + ep_cg * 72);

                #pragma unroll
                for (int f = 0; f < 18; f++) {
                    float t[4];
                    #pragma unroll
                    for (int q = 0; q < 4; q++) {
                        const int idx = 4 * f + q;     // compile-time
                        const int u = idx / 9;
                        const int j = idx % 9;
                        t[q] = sh9[j] * wv[3 * u + WIDX[j]];
                    }
                    float4 v;
                    v.x = t[0]; v.y = t[1]; v.z = t[2]; v.w = t[3];
                    __stcs(ob + f, v);
                }
            }
        }

        // ---- STS prefetched A for next tile (A_t disjoint from wr_s) ----
        #pragma unroll
        for (int it = 0; it < 4; it++) {
            const int f  = it * NTHREADS + tid;
            const int e  = f >> 4;
            const int kq = f & 15;
            const float vv[4] = {pr[it].x, pr[it].y, pr[it].z, pr[it].w};
            #pragma unroll
            for (int i = 0; i < 4; i++) {
                const int k  = kq * 4 + i;
                const int sw = ((k & 7) ^ ((k >> 3) & 7)) << 2;
                A_t[k * E_TILE + (e ^ sw)] = vv[i];
            }
        }

        __syncthreads();   // (E) A_t(next) visible; epilogue reads of wr_s done
    }
}

extern "C" void kernel_launch(void* const* d_in, const int* in_sizes, int n_in,
                              void* d_out, int out_size)
{
    const float* edge_vec = (const float*)d_in[0];
    const float* EI       = (const float*)d_in[1];
    const float* Wg       = (const float*)d_in[2];
    float* out            = (float*)d_out;

    const int E      = in_sizes[0] / 3;
    const int ntiles = (E + E_TILE - 1) / E_TILE;

    const int smem_bytes = SMEM_FLOATS * sizeof(float);  // 114688 B
    cudaFuncSetAttribute(embed_kernel,
                         cudaFuncAttributeMaxDynamicSharedMemorySize,
                         smem_bytes);

    int grid = 304;  // 2 CTAs/SM persistent on 152-SM GB300
    if (grid > ntiles) grid = ntiles;

    embed_kernel<<<grid, NTHREADS, smem_bytes>>>(edge_vec, EI, Wg, out, E, ntiles);
}

// round 16
// speedup vs baseline: 1.6842x; 1.0063x over previous
#include <cuda_runtime.h>

// ---------------------------------------------------------------------------
// TwoBodySphericalHarmonicTensorEmbed
//   out[e, c, j] = sh_j(edge_vec[e]) * w[e, c, widx[j]]
//   w[e, c, i]   = dot(edge_invariants[e, :64], W_lin[:, 3c+i])
//   widx = {0,1,1,1,2,2,2,2,2}
//
// R16: exactly R11's compute structure (the 282.7us best: 12 f32x2 acc,
// 8 edges/thread, [n][e] stride-33 w staging, 18x STG.128 epilogue) but at
// 3 CTAs/SM for latency hiding: A tile aliased into the w-staging region
// (smem 73.9KB/CTA -> 3 fit in 228KB), reg cap 85 via launch_bounds(256,3),
// GEMM unroll 4 + two-half epilogue to stay under the cap without spills.
// ---------------------------------------------------------------------------

#define NTHREADS 256
#define E_TILE   32

// smem layout (floats)
#define W_SZ     (64 * 192)            // 12288
#define WR_OFF   (W_SZ)                // w_s: [n=192][e], stride 33
#define WS_STR   33
#define WR_SZ    (192 * WS_STR)        // 6336 ; A_t (64*32=2048) aliases front
#define SH_OFF   (WR_OFF + WR_SZ)      // sh_s: [e=32][9]
#define SH_SZ    (32 * 9)              // 288
#define SMEM_FLOATS (SH_OFF + SH_SZ)   // 18912 floats = 75648 B

__device__ __forceinline__ unsigned long long pack2(float lo, float hi) {
    unsigned long long r;
    asm("mov.b64 %0, {%1, %2};" : "=l"(r) : "f"(lo), "f"(hi));
    return r;
}
__device__ __forceinline__ void fma2(unsigned long long& d,
                                     unsigned long long a,
                                     unsigned long long b) {
    asm("fma.rn.f32x2 %0, %1, %2, %0;" : "+l"(d) : "l"(a), "l"(b));
}
__device__ __forceinline__ void unpack2(unsigned long long v, float& lo, float& hi) {
    asm("mov.b64 {%0, %1}, %2;" : "=f"(lo), "=f"(hi) : "l"(v));
}

__global__ void __launch_bounds__(NTHREADS, 3)
embed_kernel(const float* __restrict__ edge_vec,
             const float* __restrict__ EI,       // [E, 64]
             const float* __restrict__ Wg,       // [64, 192]
             float* __restrict__ out,            // [E, 64, 9]
             int E, int ntiles)
{
    extern __shared__ float smem[];
    float* W_s  = smem;
    float* w_s  = smem + WR_OFF;       // [n][e], stride WS_STR
    float* A_t  = w_s;                 // ALIAS: [k=64][e=32]; dead before w_s
                                       // is written (barrier C orders it)
    float* sh_s = smem + SH_OFF;

    const int tid = threadIdx.x;

    // ---- stage W_lin once per block (persistent grid) ----
    {
        const float4* wg4 = reinterpret_cast<const float4*>(Wg);
        float4* ws4 = reinterpret_cast<float4*>(W_s);
        #pragma unroll
        for (int i = 0; i < 12; i++)
            ws4[tid + i * NTHREADS] = wg4[tid + i * NTHREADS];
    }

    // GEMM mapping: channel c (0..63), 8-edge group (eg 0..3)
    const int c  = tid & 63;
    const int eg = tid >> 6;
    const int e0 = eg * 8;

    // epilogue mapping: edge (0..31), 8-channel group (0..7)
    const int ep_e  = tid >> 3;
    const int ep_cg = tid & 7;

    for (int tile = blockIdx.x; tile < ntiles; tile += gridDim.x) {
        const int ebase = tile * E_TILE;

        __syncthreads();  // (A) prev epilogue done reading w_s before A_t clobbers

        // ---- stage A tile, transposed + XOR-swizzled: A_t[k][e ^ sw(k)] ----
        #pragma unroll
        for (int iter = 0; iter < 2; iter++) {
            const int f  = iter * NTHREADS + tid;   // 0..511
            const int e  = f >> 4;                  // 0..31
            const int kq = f & 15;                  // float4 index along k
            const int eglob = ebase + e;
            float4 v = make_float4(0.f, 0.f, 0.f, 0.f);
            if (eglob < E)
                v = *reinterpret_cast<const float4*>(EI + (size_t)eglob * 64 + kq * 4);
            const float vv[4] = {v.x, v.y, v.z, v.w};
            #pragma unroll
            for (int i = 0; i < 4; i++) {
                const int k  = kq * 4 + i;
                const int sw = ((k & 7) ^ ((k >> 3) & 7)) << 2;
                A_t[k * 32 + (e ^ sw)] = vv[i];
            }
        }

        // ---- spherical harmonics for the 32 edges ----
        if (tid < 32) {
            const int eglob = ebase + tid;
            float s[9] = {0.f, 0.f, 0.f, 0.f, 0.f, 0.f, 0.f, 0.f, 0.f};
            if (eglob < E) {
                const float vx = edge_vec[(size_t)eglob * 3 + 0];
                const float vy = edge_vec[(size_t)eglob * 3 + 1];
                const float vz = edge_vec[(size_t)eglob * 3 + 2];
                const float inv = rsqrtf(vx * vx + vy * vy + vz * vz);
                const float x = vx * inv, y = vy * inv, z = vz * inv;
                const float SQ3  = 1.7320508075688772f;
                const float SQ5  = 2.2360679774997896f;
                const float SQ15 = 3.8729833462074170f;
                s[0] = 1.0f;
                s[1] = SQ3 * x;
                s[2] = SQ3 * y;
                s[3] = SQ3 * z;
                s[4] = SQ15 * x * z;
                s[5] = SQ15 * x * y;
                s[6] = SQ5 * (y * y - 0.5f * (x * x + z * z));
                s[7] = SQ15 * y * z;
                s[8] = (SQ15 * 0.5f) * (z * z - x * x);
            }
            #pragma unroll
            for (int j = 0; j < 9; j++) sh_s[tid * 9 + j] = s[j];
        }

        __syncthreads();  // (B) A_t + sh_s visible

        // ---- GEMM: acc[ir][p] = f32x2 over edge pairs (e0+2p, e0+2p+1) ----
        unsigned long long acc[3][4];
        #pragma unroll
        for (int ir = 0; ir < 3; ir++)
            #pragma unroll
            for (int p = 0; p < 4; p++) acc[ir][p] = 0ull;

        #pragma unroll 4
        for (int k = 0; k < 64; k++) {
            const int sw = ((k & 7) ^ ((k >> 3) & 7)) << 2;
            const float* arow = A_t + k * 32;
            const ulonglong2 a01 =
                *reinterpret_cast<const ulonglong2*>(arow + (e0 ^ sw));
            const ulonglong2 a23 =
                *reinterpret_cast<const ulonglong2*>(arow + ((e0 + 4) ^ sw));
            const float* wr = W_s + k * 192 + 3 * c;   // banks 3c distinct mod 32
            const unsigned long long pw0 = pack2(wr[0], wr[0]);
            const unsigned long long pw1 = pack2(wr[1], wr[1]);
            const unsigned long long pw2 = pack2(wr[2], wr[2]);
            fma2(acc[0][0], a01.x, pw0); fma2(acc[0][1], a01.y, pw0);
            fma2(acc[0][2], a23.x, pw0); fma2(acc[0][3], a23.y, pw0);
            fma2(acc[1][0], a01.x, pw1); fma2(acc[1][1], a01.y, pw1);
            fma2(acc[1][2], a23.x, pw1); fma2(acc[1][3], a23.y, pw1);
            fma2(acc[2][0], a01.x, pw2); fma2(acc[2][1], a01.y, pw2);
            fma2(acc[2][2], a23.x, pw2); fma2(acc[2][3], a23.y, pw2);
        }

        __syncthreads();  // (C) all GEMM reads of A_t done; w_s may clobber it

        // ---- write w to smem: w_s[n][e], n = 3c+ir (conflict-free) ----
        #pragma unroll
        for (int ir = 0; ir < 3; ir++) {
            float* base = w_s + (3 * c + ir) * WS_STR + e0;
            #pragma unroll
            for (int p = 0; p < 4; p++) {
                float lo, hi;
                unpack2(acc[ir][p], lo, hi);
                base[2 * p]     = lo;
                base[2 * p + 1] = hi;
            }
        }

        __syncthreads();  // (D) w_s visible

        // ---- epilogue: thread = (edge, 8-channel group), two 4-channel halves
        const int eglob = ebase + ep_e;
        if (eglob < E) {
            float sh9[9];
            #pragma unroll
            for (int j = 0; j < 9; j++) sh9[j] = sh_s[ep_e * 9 + j];

            const int WIDX[9] = {0, 1, 1, 1, 2, 2, 2, 2, 2};

            #pragma unroll
            for (int half = 0; half < 2; half++) {
                // 12 w values = 4 channels x 3 irreps
                float wv[12];
                #pragma unroll
                for (int m = 0; m < 12; m++)
                    wv[m] = w_s[(ep_cg * 24 + half * 12 + m) * WS_STR + ep_e];

                float4* ob = reinterpret_cast<float4*>(
                    out + (size_t)eglob * 576 + ep_cg * 72 + half * 36);

                #pragma unroll
                for (int f = 0; f < 9; f++) {
                    float t[4];
                    #pragma unroll
                    for (int q = 0; q < 4; q++) {
                        const int idx = 4 * f + q;     // 0..35 (compile-time)
                        const int u = idx / 9;         // local channel 0..3
                        const int j = idx % 9;
                        t[q] = sh9[j] * wv[3 * u + WIDX[j]];
                    }
                    float4 v;
                    v.x = t[0]; v.y = t[1]; v.z = t[2]; v.w = t[3];
                    __stcs(ob + f, v);  // streaming: output never re-read
                }
            }
        }
    }
}

extern "C" void kernel_launch(void* const* d_in, const int* in_sizes, int n_in,
                              void* d_out, int out_size)
{
    const float* edge_vec = (const float*)d_in[0];
    const float* EI       = (const float*)d_in[1];
    const float* Wg       = (const float*)d_in[2];
    float* out            = (float*)d_out;

    const int E      = in_sizes[0] / 3;
    const int ntiles = (E + E_TILE - 1) / E_TILE;

    const int smem_bytes = SMEM_FLOATS * sizeof(float);  // 75648 B
    cudaFuncSetAttribute(embed_kernel,
                         cudaFuncAttributeMaxDynamicSharedMemorySize,
                         smem_bytes);

    int grid = 456;  // 3 CTAs/SM persistent on 152-SM GB300
    if (grid > ntiles) grid = ntiles;

    embed_kernel<<<grid, NTHREADS, smem_bytes>>>(edge_vec, EI, Wg, out, E, ntiles);
}